// round 15
// baseline (speedup 1.0000x reference)
#include <cuda_runtime.h>

#define Bn   1024
#define Kseg 160
#define WS   12
#define G    36
#define DH   1024
#define TPAD 168            // Kseg + 8 prefetch pad
#define STR4 (Bn * WS)      // float4 stride between t slots

typedef unsigned long long u64;

// Scratch (static device globals — no allocation)
__device__ float4 g_gi[TPAD * Bn * WS];        // [t][b][j] = {0.5*r, 0.5*z, n_raw, 0}
__device__ float4 g_pegi4[Kseg * WS];          // [k][j] = {0.5*pr, 0.5*pz, pn_raw, 0}
__device__ float4 g_wdec[(Kseg + 2) * WS * 4]; // [k][j][4] (+2 pad k-slots)

// Warp-uniform weights -> constant path
__constant__ float cWih[G * WS];
__constant__ float cbih[G];
__constant__ float cbhh[G];

__device__ __forceinline__ float ftanh(float x) {
    float y; asm("tanh.approx.f32 %0, %1;" : "=f"(y) : "f"(x)); return y;
}
__device__ __forceinline__ u64 pk(float lo, float hi) {
    u64 r; asm("mov.b64 %0, {%1, %2};" : "=l"(r) : "f"(lo), "f"(hi)); return r;
}
__device__ __forceinline__ void upk(u64 v, float& lo, float& hi) {
    asm("mov.b64 {%0, %1}, %2;" : "=f"(lo), "=f"(hi) : "l"(v));
}
__device__ __forceinline__ u64 ffma2(u64 a, u64 b, u64 c) {
    u64 d; asm("fma.rn.f32x2 %0, %1, %2, %3;" : "=l"(d) : "l"(a), "l"(b), "l"(c));
    return d;
}
__device__ __forceinline__ float4 ldgcs(const float4* p) {   // streaming load
    float4 v;
    asm("ld.global.cs.v4.f32 {%0,%1,%2,%3}, [%4];"
        : "=f"(v.x), "=f"(v.y), "=f"(v.z), "=f"(v.w) : "l"(p));
    return v;
}

// ---------------------------------------------------------------------------
// Prep kernel (unchanged from R14): 0..639 enc+gi, 640..799 weff, 800 pegi.
// ---------------------------------------------------------------------------
__global__ void __launch_bounds__(256) prep_kernel(
        const float* __restrict__ x,
        const float* __restrict__ enc_W,
        const float* __restrict__ enc_b,
        const float* __restrict__ dec_W1,
        const float* __restrict__ dec_b1,
        const float* __restrict__ dec_W2,
        const float* __restrict__ dec_b2) {
    __shared__ float sraw[DH * WS];   // 48 KB

    if (blockIdx.x < 640) {
        float* sEW = sraw;
        float* sEB = sraw + 144;
        float* sg  = sraw + 192;
        int k = blockIdx.x >> 2;
        int bbase = (blockIdx.x & 3) << 8;
        int b = bbase + threadIdx.x;

        {
            int t = threadIdx.x;
            if (t < WS * WS) sEW[t] = enc_W[k * (WS * WS) + t];
            if (t < WS) sEB[t] = enc_b[k * WS + t];
        }
        __syncthreads();

        const float4* xr4 = (const float4*)(x + (size_t)b * 1920 + k * WS);
        float4 x0 = xr4[0], x1 = xr4[1], x2 = xr4[2];
        float xv[WS] = {x0.x, x0.y, x0.z, x0.w, x1.x, x1.y, x1.z, x1.w,
                        x2.x, x2.y, x2.z, x2.w};

        float xs[WS];
#pragma unroll
        for (int o = 0; o < WS; ++o) {
            float a = sEB[o];
#pragma unroll
            for (int i = 0; i < WS; ++i) a = fmaf(xv[i], sEW[i * WS + o], a);
            xs[o] = fmaxf(a, 0.0f);
        }

        float* sgr = sg + threadIdx.x * 37;
#pragma unroll
        for (int g = 0; g < G; ++g) {
            float a = cbih[g] + ((g < 24) ? cbhh[g] : 0.0f);
#pragma unroll
            for (int o = 0; o < WS; ++o) a = fmaf(xs[o], cWih[g * WS + o], a);
            sgr[g] = a;
        }
        __syncthreads();

        float4* dst = g_gi + ((size_t)k * Bn + bbase) * WS;
        for (int i = threadIdx.x; i < 256 * WS; i += 256) {
            int bl = i / WS;
            int j = i - bl * WS;
            const float* s = sg + bl * 37;
            dst[i] = make_float4(0.5f * s[j], 0.5f * s[12 + j], s[24 + j], 0.0f);
        }
        return;
    }

    if (blockIdx.x == 800) {
        int k = threadIdx.x;
        if (k >= Kseg) return;
        float pe[WS];
        const float c = -9.210340371976184f / 12.0f;
#pragma unroll
        for (int j = 0; j < 6; ++j) {
            float div = expf(c * (float)(2 * j));
            float ang = (float)k * div;
            pe[2 * j]     = sinf(ang);
            pe[2 * j + 1] = cosf(ang);
        }
        float ch = sinf((float)k);
#pragma unroll
        for (int o = 0; o < WS; ++o) pe[o] += ch;
        float pg[G];
#pragma unroll
        for (int g = 0; g < G; ++g) {
            float a = 0.0f;
#pragma unroll
            for (int o = 0; o < WS; ++o) a = fmaf(pe[o], cWih[g * WS + o], a);
            pg[g] = a;
        }
#pragma unroll
        for (int j = 0; j < WS; ++j)
            g_pegi4[k * WS + j] = make_float4(0.5f * pg[j], 0.5f * pg[12 + j],
                                              pg[24 + j], 0.0f);
        return;
    }

    {
        float* w2s = sraw;
        int k = blockIdx.x - 640;
        const float4* W24 = (const float4*)(dec_W2 + (size_t)k * DH * WS);
        float4* w2s4 = (float4*)w2s;
        for (int i = threadIdx.x; i < DH * WS / 4; i += 256) w2s4[i] = W24[i];
        __syncthreads();

        float* wdecF = (float*)g_wdec;
        int t = threadIdx.x;
        if (t < 144) {
            int d = t / WS, o = t - (t / WS) * WS;
            const float4* w14 = (const float4*)(dec_W1 + ((size_t)k * WS + d) * DH);
            float a0 = 0.f, a1 = 0.f, a2 = 0.f, a3 = 0.f;
            float a4 = 0.f, a5 = 0.f, a6 = 0.f, a7 = 0.f;
            for (int q = 0; q < DH / 4; q += 2) {
                float4 u = w14[q], v = w14[q + 1];
                int h = q * 4;
                a0 = fmaf(u.x, w2s[(h + 0) * WS + o], a0);
                a1 = fmaf(u.y, w2s[(h + 1) * WS + o], a1);
                a2 = fmaf(u.z, w2s[(h + 2) * WS + o], a2);
                a3 = fmaf(u.w, w2s[(h + 3) * WS + o], a3);
                a4 = fmaf(v.x, w2s[(h + 4) * WS + o], a4);
                a5 = fmaf(v.y, w2s[(h + 5) * WS + o], a5);
                a6 = fmaf(v.z, w2s[(h + 6) * WS + o], a6);
                a7 = fmaf(v.w, w2s[(h + 7) * WS + o], a7);
            }
            wdecF[((size_t)k * WS + o) * 16 + d] =
                ((a0 + a1) + (a2 + a3)) + ((a4 + a5) + (a6 + a7));
        } else if (t < 156) {
            int o = t - 144;
            const float4* b14 = (const float4*)(dec_b1 + (size_t)k * DH);
            float a0 = dec_b2[k * WS + o], a1 = 0.f, a2 = 0.f, a3 = 0.f;
            for (int q = 0; q < DH / 4; ++q) {
                float4 u = b14[q];
                int h = q * 4;
                a0 = fmaf(u.x, w2s[(h + 0) * WS + o], a0);
                a1 = fmaf(u.y, w2s[(h + 1) * WS + o], a1);
                a2 = fmaf(u.z, w2s[(h + 2) * WS + o], a2);
                a3 = fmaf(u.w, w2s[(h + 3) * WS + o], a3);
            }
            wdecF[((size_t)k * WS + o) * 16 + 12] = (a0 + a1) + (a2 + a3);
        }
    }
}

// ---------------------------------------------------------------------------
// RNN + fused decoder. TWO rows per 16-lane group, statement-interleaved so
// the two dependency chains fill each other's stall cycles. Weights (gate,
// decoder, pegi) shared across the pair. 4 rows/warp total.
// ---------------------------------------------------------------------------
__device__ __forceinline__ void bcast2d(float hA, float hB, u64* hpA, u64* hpB) {
#pragma unroll
    for (int m = 0; m < 6; ++m) {
        float a0 = __shfl_sync(0xffffffffu, hA, 2 * m, 16);
        float b0 = __shfl_sync(0xffffffffu, hB, 2 * m, 16);
        float a1 = __shfl_sync(0xffffffffu, hA, 2 * m + 1, 16);
        float b1 = __shfl_sync(0xffffffffu, hB, 2 * m + 1, 16);
        hpA[m] = pk(a0, a1);
        hpB[m] = pk(b0, b1);
    }
}

// Interleaved dual-row gate update (modifies hA, hB in place).
__device__ __forceinline__ void gates2d(
        const u64* hpA, const u64* hpB,
        float grA, float gzA, float gnA,
        float grB, float gzB, float gnB,
        float bnp, const u64* wR, const u64* wZ, const u64* wN,
        float& hA, float& hB) {
    u64 aRA = pk(grA, 0.f), aRB = pk(grB, 0.f);
    u64 aZA = pk(gzA, 0.f), aZB = pk(gzB, 0.f);
    u64 aNA = pk(bnp, 0.f), aNB = pk(bnp, 0.f);
#pragma unroll
    for (int m = 0; m < 6; ++m) {
        aRA = ffma2(wR[m], hpA[m], aRA);
        aRB = ffma2(wR[m], hpB[m], aRB);
        aZA = ffma2(wZ[m], hpA[m], aZA);
        aZB = ffma2(wZ[m], hpB[m], aZB);
        aNA = ffma2(wN[m], hpA[m], aNA);
        aNB = ffma2(wN[m], hpB[m], aNB);
    }
    float rlA, rhA, zlA, zhA, nlA, nhA;
    float rlB, rhB, zlB, zhB, nlB, nhB;
    upk(aRA, rlA, rhA); upk(aRB, rlB, rhB);
    upk(aZA, zlA, zhA); upk(aZB, zlB, zhB);
    upk(aNA, nlA, nhA); upk(aNB, nlB, nhB);
    float rA = fmaf(0.5f, ftanh(rlA + rhA), 0.5f);
    float rB = fmaf(0.5f, ftanh(rlB + rhB), 0.5f);
    float zA = fmaf(0.5f, ftanh(zlA + zhA), 0.5f);
    float zB = fmaf(0.5f, ftanh(zlB + zhB), 0.5f);
    float nA = ftanh(fmaf(rA, nlA + nhA, gnA));
    float nB = ftanh(fmaf(rB, nlB + nhB, gnB));
    hA = fmaf(zA, hA - nA, nA);
    hB = fmaf(zB, hB - nB, nB);
}

__device__ __forceinline__ float decacc2u(const u64* hp, const u64* W, float be) {
    u64 acc = pk(be, 0.f);
#pragma unroll
    for (int m = 0; m < 6; ++m) acc = ffma2(W[m], hp[m], acc);
    float lo, hi; upk(acc, lo, hi);
    return lo + hi;
}

__global__ void __launch_bounds__(64) rnn_kernel(const float* __restrict__ Whh,
                                                 const float* __restrict__ bhh,
                                                 float* __restrict__ out) {
    __shared__ float4 pegis[Kseg * WS];        // 30 KB static
    int lane16 = threadIdx.x & 15;
    int grp = threadIdx.x >> 4;                // 0..3
    int rowA = (blockIdx.x * 4 + grp) * 2;     // 0..1022 (even)
    bool act = (lane16 < WS);
    int j = act ? lane16 : (WS - 1);

    u64 wR[6], wZ[6], wN[6];
#pragma unroll
    for (int m = 0; m < 6; ++m) {
        wR[m] = pk(0.5f * Whh[j * 12 + 2 * m],        0.5f * Whh[j * 12 + 2 * m + 1]);
        wZ[m] = pk(0.5f * Whh[(12 + j) * 12 + 2 * m], 0.5f * Whh[(12 + j) * 12 + 2 * m + 1]);
        wN[m] = pk(Whh[(24 + j) * 12 + 2 * m],        Whh[(24 + j) * 12 + 2 * m + 1]);
    }
    float bnp = bhh[24 + j];

    for (int i = threadIdx.x; i < Kseg * WS; i += 64) pegis[i] = g_pegi4[i];
    __syncthreads();

    const float4* pA = g_gi + (size_t)rowA * WS + j;   // row B = +WS float4s
    float hA = 0.0f, hB = 0.0f;

    // ---------------- phase 1: first GRU, depth-4 ring per row --------------
    {
        float4 aA0 = ldgcs(pA),            aB0 = ldgcs(pA + WS);
        float4 aA1 = ldgcs(pA + STR4),     aB1 = ldgcs(pA + STR4 + WS);
        float4 aA2 = ldgcs(pA + 2 * STR4), aB2 = ldgcs(pA + 2 * STR4 + WS);
        float4 aA3 = ldgcs(pA + 3 * STR4), aB3 = ldgcs(pA + 3 * STR4 + WS);
        const float4* q = pA + 4 * STR4;

#define DSTEP1(AA, AB, QOFF)                                                \
        {                                                                   \
            u64 hpA[6], hpB[6];                                             \
            bcast2d(hA, hB, hpA, hpB);                                      \
            gates2d(hpA, hpB, AA.x, AA.y, AA.z, AB.x, AB.y, AB.z,           \
                    bnp, wR, wZ, wN, hA, hB);                               \
            AA = ldgcs(q + (QOFF));                                         \
            AB = ldgcs(q + (QOFF) + WS);                                    \
        }

        for (int t = 0; t < Kseg; t += 4) {
            DSTEP1(aA0, aB0, 0);
            DSTEP1(aA1, aB1, STR4);
            DSTEP1(aA2, aB2, 2 * STR4);
            DSTEP1(aA3, aB3, 3 * STR4);
            q += 4 * STR4;
        }
#undef DSTEP1
    }

    // ---------------- phase 2: second GRU + fused decoder -------------------
    float* outpA = out + (size_t)rowA * 1920 + j;
    float* outpB = outpA + 1920;
    const float4* wgj = g_wdec + (size_t)j * 4;       // + k*48 per step

#define LOADW(W, BIAS, KK)                                                  \
    {                                                                       \
        const longlong2* _p = (const longlong2*)(wgj + (size_t)(KK) * 48);  \
        longlong2 l0 = _p[0], l1 = _p[1], l2 = _p[2];                       \
        W[0] = (u64)l0.x; W[1] = (u64)l0.y;                                 \
        W[2] = (u64)l1.x; W[3] = (u64)l1.y;                                 \
        W[4] = (u64)l2.x; W[5] = (u64)l2.y;                                 \
        BIAS = wgj[(size_t)(KK) * 48 + 3].x;                                \
    }

    u64 WE[6], WO[6];
    float beE, beO;
    LOADW(WE, beE, 0);       // consumed at t=1
    LOADW(WO, beO, 1);       // consumed at t=2

    {
        float4 aA0 = ldgcs(pA),            aB0 = ldgcs(pA + WS);
        float4 aA1 = ldgcs(pA + STR4),     aB1 = ldgcs(pA + STR4 + WS);
        float4 aA2 = ldgcs(pA + 2 * STR4), aB2 = ldgcs(pA + 2 * STR4 + WS);
        float4 aA3 = ldgcs(pA + 3 * STR4), aB3 = ldgcs(pA + 3 * STR4 + WS);
        const float4* q = pA + 4 * STR4;
        const float4* pg = pegis + j;

#define DSTEP2(AA, AB, PV, TT, QOFF, WB, BB)                                \
        {                                                                   \
            u64 hpA[6], hpB[6];                                             \
            bcast2d(hA, hB, hpA, hpB);                                      \
            if (act && (TT) > 0) {                                          \
                float oaA = decacc2u(hpA, WB, BB);                          \
                float oaB = decacc2u(hpB, WB, BB);                          \
                outpA[((TT) - 1) * 12] = oaA;                               \
                outpB[((TT) - 1) * 12] = oaB;                               \
            }                                                               \
            gates2d(hpA, hpB,                                               \
                    AA.x + PV.x, AA.y + PV.y, AA.z + PV.z,                  \
                    AB.x + PV.x, AB.y + PV.y, AB.z + PV.z,                  \
                    bnp, wR, wZ, wN, hA, hB);                               \
            AA = ldgcs(q + (QOFF));                                         \
            AB = ldgcs(q + (QOFF) + WS);                                    \
            LOADW(WB, BB, (TT) + 1);                                        \
        }

        for (int t = 0; t < Kseg; t += 4) {
            float4 p0 = pg[0], p1 = pg[WS], p2 = pg[2 * WS], p3 = pg[3 * WS];
            pg += 4 * WS;
            DSTEP2(aA0, aB0, p0, t + 0, 0,        WO, beO);
            DSTEP2(aA1, aB1, p1, t + 1, STR4,     WE, beE);
            DSTEP2(aA2, aB2, p2, t + 2, 2 * STR4, WO, beO);
            DSTEP2(aA3, aB3, p3, t + 3, 3 * STR4, WE, beE);
            q += 4 * STR4;
        }
#undef DSTEP2

        // tail: out for t = Kseg-1 from WO (loaded at step 158)
        u64 hpA[6], hpB[6];
        bcast2d(hA, hB, hpA, hpB);
        if (act) {
            outpA[(Kseg - 1) * 12] = decacc2u(hpA, WO, beO);
            outpB[(Kseg - 1) * 12] = decacc2u(hpB, WO, beO);
        }
    }
#undef LOADW
}

// ---------------------------------------------------------------------------
extern "C" void kernel_launch(void* const* d_in, const int* in_sizes, int n_in,
                              void* d_out, int out_size) {
    const float* x     = (const float*)d_in[0];
    const float* enc_W = (const float*)d_in[1];
    const float* enc_b = (const float*)d_in[2];
    const float* Wih   = (const float*)d_in[3];
    const float* Whh   = (const float*)d_in[4];
    const float* bih   = (const float*)d_in[5];
    const float* bhh   = (const float*)d_in[6];
    const float* dW1   = (const float*)d_in[7];
    const float* db1   = (const float*)d_in[8];
    const float* dW2   = (const float*)d_in[9];
    const float* db2   = (const float*)d_in[10];
    float* out = (float*)d_out;

    cudaMemcpyToSymbolAsync(cWih, Wih, G * WS * sizeof(float), 0,
                            cudaMemcpyDeviceToDevice);
    cudaMemcpyToSymbolAsync(cbih, bih, G * sizeof(float), 0,
                            cudaMemcpyDeviceToDevice);
    cudaMemcpyToSymbolAsync(cbhh, bhh, G * sizeof(float), 0,
                            cudaMemcpyDeviceToDevice);

    prep_kernel<<<801, 256>>>(x, enc_W, enc_b, dW1, db1, dW2, db2);
    rnn_kernel<<<128, 64>>>(Whh, bhh, out);   // 4 groups x 2 rows per block
}